// round 5
// baseline (speedup 1.0000x reference)
#include <cuda_runtime.h>
#include <math.h>

#define D 128
#define T 64
#define BATCH 512
#define EPS 1e-5f
#define FULLMASK 0xffffffffu

#define SV_STRIDE 132   // float4-aligned, conflict-free row float4 loads
#define VT_STRIDE 129   // conflict-free scalar column (=vT row) loads

// -------- scratch (device globals; no allocation allowed) --------
__device__ float g_v[D * D];                 // row-normalized W
__device__ float g_rT[(T - 1) * BATCH * D];  // returns transposed: [t][b][d]
__device__ float g_h0T[BATCH * D];           // input[:,0,:] transposed: [b][d]
__device__ float g_outT[T * BATCH * D];      // output transposed: [t][b][d]

// -------- v = W / max(||W_row||, 1e-12) --------
__global__ void prep_v_kernel(const float* __restrict__ W) {
    int i = threadIdx.x;  // row
    float ss = 0.f;
#pragma unroll 8
    for (int j = 0; j < D; j++) {
        float w = W[i * D + j];
        ss += w * w;
    }
    float nrm = fmaxf(sqrtf(ss), 1e-12f);
    for (int j = 0; j < D; j++) g_v[i * D + j] = W[i * D + j] / nrm;
}

// -------- transpose returns (and input t=0 slice) into [t][b][d] --------
__global__ void transpose_in_kernel(const float* __restrict__ inp,
                                    const float* __restrict__ ret) {
    __shared__ float tile[32][33];
    int z = blockIdx.z;
    int b0 = blockIdx.x * 32, d0 = blockIdx.y * 32;
    int tx = threadIdx.x, ty = threadIdx.y;  // (32, 8)
    const float* srcbase;
    float* dst;
    if (z < T - 1) {
        srcbase = ret + (size_t)z * BATCH;
        dst = g_rT + (size_t)z * BATCH * D;
    } else {
        srcbase = inp;
        dst = g_h0T;
    }
#pragma unroll
    for (int i = 0; i < 32; i += 8)
        tile[ty + i][tx] = srcbase[(size_t)(d0 + ty + i) * T * BATCH + (b0 + tx)];
    __syncthreads();
#pragma unroll
    for (int i = 0; i < 32; i += 8)
        dst[(size_t)(b0 + ty + i) * D + (d0 + tx)] = tile[tx][ty + i];
}

// -------- transpose outT [t][b][d] -> out (D,T,B); also emit h_last --------
__global__ void transpose_out_kernel(float* __restrict__ out) {
    __shared__ float tile[32][33];
    int t = blockIdx.z;
    int b0 = blockIdx.x * 32, d0 = blockIdx.y * 32;
    int tx = threadIdx.x, ty = threadIdx.y;
    const float* src = g_outT + (size_t)t * BATCH * D;
#pragma unroll
    for (int i = 0; i < 32; i += 8)
        tile[ty + i][tx] = src[(size_t)(b0 + ty + i) * D + (d0 + tx)];
    __syncthreads();
#pragma unroll
    for (int i = 0; i < 32; i += 8) {
        float val = tile[tx][ty + i];
        int d = d0 + ty + i;
        int b = b0 + tx;
        out[(size_t)d * T * BATCH + (size_t)t * BATCH + b] = val;
        if (t == T - 1)
            out[(size_t)D * T * BATCH + (size_t)d * BATCH + b] = val;
    }
}

// -------- main recurrence: 1 warp per batch column, thread owns 4 dims --------
__global__ void __launch_bounds__(128) rnn_main_kernel(const float* __restrict__ tgt_g,
                                                       const float* __restrict__ b_g) {
    extern __shared__ float smem[];
    float* sv = smem;                              // [128][132] row-major (float4 matvec)
    float* svT = smem + D * SV_STRIDE;             // [128][129] transposed (column access)
    float* xb = svT + D * VT_STRIDE;               // per-warp x buffer: [4][128]

    int tid = threadIdx.x, lane = tid & 31, warp = tid >> 5;

    // fill both smem copies of v
    for (int idx = tid; idx < D * D; idx += 128) {
        int r = idx >> 7, c = idx & 127;
        float val = g_v[idx];
        sv[r * SV_STRIDE + c] = val;
        svT[c * VT_STRIDE + r] = val;
    }
    __syncthreads();

    int col = blockIdx.x * 4 + warp;  // grid=128 -> col in [0,512)
    float* xw = xb + warp * D;

    float h4[4], tgt4[4], ab4[4], rvd4[4], bp4[4], bn4[4];
#pragma unroll
    for (int q = 0; q < 4; q++) {
        int d = lane + 32 * q;
        tgt4[q] = tgt_g[d];
        ab4[q] = fabsf(b_g[d]);
        rvd4[q] = 1.0f / sv[d * SV_STRIDE + d];
        bp4[q] = ab4[q] + EPS;
        bn4[q] = -ab4[q] - EPS;
        float h0 = g_h0T[(size_t)col * D + d];
        h4[q] = h0;
        g_outT[(size_t)col * D + d] = h0;  // t = 0 slice
    }

    // prefetch r for step t=1 (index 0)
    float rp4[4];
#pragma unroll
    for (int q = 0; q < 4; q++)
        rp4[q] = g_rT[(size_t)col * D + (lane + 32 * q)];

    for (int t = 1; t < T; t++) {
        // ---- adj = h*(1+r) / (1 + sum(h*r)) ----
        float r4[4], adj4[4], x4[4];
        float acc = 0.f;
#pragma unroll
        for (int q = 0; q < 4; q++) {
            r4[q] = rp4[q];
            acc += h4[q] * r4[q];
        }
#pragma unroll
        for (int o = 16; o; o >>= 1) acc += __shfl_xor_sync(FULLMASK, acc, o);
        float denom = 1.0f + acc;
#pragma unroll
        for (int q = 0; q < 4; q++) {
            adj4[q] = h4[q] * (1.0f + r4[q]) / denom;
            x4[q] = adj4[q] - tgt4[q];
            xw[lane + 32 * q] = x4[q];
        }
        __syncwarp();

        // prefetch next step's r while the matvec runs
        if (t < T - 1) {
#pragma unroll
            for (int q = 0; q < 4; q++)
                rp4[q] = g_rT[((size_t)t * BATCH + col) * D + (lane + 32 * q)];
        }

        // ---- s = v @ (adj - pi_bar), float4 loads ----
        float s4[4] = {0.f, 0.f, 0.f, 0.f};
        const float4* xw4 = (const float4*)xw;
#pragma unroll 8
        for (int i4 = 0; i4 < D / 4; i4++) {
            float4 x = xw4[i4];
#pragma unroll
            for (int q = 0; q < 4; q++) {
                float4 vv = *(const float4*)&sv[(lane + 32 * q) * SV_STRIDE + 4 * i4];
                s4[q] = fmaf(vv.x, x.x, s4[q]);
                s4[q] = fmaf(vv.y, x.y, s4[q]);
                s4[q] = fmaf(vv.z, x.z, s4[q]);
                s4[q] = fmaf(vv.w, x.w, s4[q]);
            }
        }
        __syncwarp();  // xw reads done before next-iteration writes

        // ---- delta + feas0 ----
        float del4[4];
        bool loc = true;
#pragma unroll
        for (int q = 0; q < 4; q++) {
            float s = s4[q];
            float num = 0.f;
            if (s > ab4[q]) num = ab4[q] - s;
            else if (s < -ab4[q]) num = -ab4[q] - s;
            del4[q] = num * rvd4[q];
            loc = loc && (s < bp4[q]) && (s > bn4[q]);
        }
        bool feas0 = __all_sync(FULLMASK, loc);
        bool judge = feas0;

        // ---- judge: any single-coordinate fix feasible? (ballot over nonzero deltas)
        if (!judge) {
#pragma unroll
            for (int sl = 0; sl < 4; sl++) {
                if (judge) continue;
                unsigned mask = __ballot_sync(FULLMASK, del4[sl] != 0.f);
                while (mask) {
                    int ln = __ffs(mask) - 1;
                    mask &= mask - 1;
                    float di = __shfl_sync(FULLMASK, del4[sl], ln);
                    int i = sl * 32 + ln;
                    bool ok = true;
#pragma unroll
                    for (int q = 0; q < 4; q++) {
                        float sn = fmaf(svT[i * VT_STRIDE + lane + 32 * q], di, s4[q]);
                        ok = ok && (sn < bp4[q]) && (sn > bn4[q]);
                    }
                    if (__all_sync(FULLMASK, ok)) { judge = true; break; }
                }
            }
        }

        float hres4[4];
        if (judge) {
            if (feas0) {
#pragma unroll
                for (int q = 0; q < 4; q++) hres4[q] = adj4[q];
            } else {
                // ---- Gauss-Seidel sweep: ballot-driven, exact vs reference's
                // strictly-increasing single pass.
                float ssl[4], ht4[4];
#pragma unroll
                for (int q = 0; q < 4; q++) { ssl[q] = s4[q]; ht4[q] = adj4[q]; }
#pragma unroll
                for (int sl = 0; sl < 4; sl++) {
                    unsigned eligible = FULLMASK;
                    while (true) {
                        float s = ssl[sl];
                        float num = 0.f;
                        if (s > ab4[sl]) num = ab4[sl] - s;
                        else if (s < -ab4[sl]) num = -ab4[sl] - s;
                        unsigned mask = __ballot_sync(FULLMASK, num != 0.f) & eligible;
                        if (!mask) break;
                        int ln = __ffs(mask) - 1;
                        float cand = num * rvd4[sl];
                        float dj = __shfl_sync(FULLMASK, cand, ln);
                        int j = sl * 32 + ln;
#pragma unroll
                        for (int q = 0; q < 4; q++)
                            ssl[q] = fmaf(svT[j * VT_STRIDE + lane + 32 * q], dj, ssl[q]);
                        if (lane == ln) ht4[sl] += dj;
                        eligible = (ln == 31) ? 0u : (FULLMASK << (ln + 1));
                    }
                }
#pragma unroll
                for (int q = 0; q < 4; q++) hres4[q] = ht4[q];
            }
        } else {
            // ---- bisection collapsed to scalar alpha on segment pi + a*(h-pi)
            float am = __int_as_float(0x7f800000);  // +inf
#pragma unroll
            for (int q = 0; q < 4; q++) {
                float as = fabsf(s4[q]);
                float lim = (as > 0.f) ? bp4[q] / as : __int_as_float(0x7f800000);
                am = fminf(am, lim);
            }
#pragma unroll
            for (int o = 16; o; o >>= 1)
                am = fminf(am, __shfl_xor_sync(FULLMASK, am, o));
            float ain = 0.f, aout = 1.f, amid = 0.5f;
#pragma unroll
            for (int it = 0; it < 10; it++) {
                amid = ain + (aout - ain) * 0.5f;
                if (amid <= am) ain = amid; else aout = amid;
            }
#pragma unroll
            for (int q = 0; q < 4; q++)
                hres4[q] = fmaf(amid, x4[q], tgt4[q]);
        }

#pragma unroll
        for (int q = 0; q < 4; q++) {
            h4[q] = hres4[q];
            g_outT[((size_t)t * BATCH + col) * D + (lane + 32 * q)] = hres4[q];
        }
    }
}

extern "C" void kernel_launch(void* const* d_in, const int* in_sizes, int n_in,
                              void* d_out, int out_size) {
    const float* inp = (const float*)d_in[0];   // (D,T,B)
    const float* tgt = (const float*)d_in[1];   // (D,)
    const float* ret = (const float*)d_in[2];   // (D,T,B)
    // d_in[3] = hidden (unused by reference)
    const float* W = (const float*)d_in[4];     // (D,D)
    const float* bb = (const float*)d_in[5];    // (D,)
    float* out = (float*)d_out;                 // D*T*B output + D*B h_last

    prep_v_kernel<<<1, 128>>>(W);

    dim3 tb(32, 8);
    transpose_in_kernel<<<dim3(BATCH / 32, D / 32, T), tb>>>(inp, ret);

    size_t smem_bytes = (size_t)(D * SV_STRIDE + D * VT_STRIDE + 4 * D) * sizeof(float);
    cudaFuncSetAttribute(rnn_main_kernel,
                         cudaFuncAttributeMaxDynamicSharedMemorySize,
                         (int)smem_bytes);
    rnn_main_kernel<<<128, 128, smem_bytes>>>(tgt, bb);

    transpose_out_kernel<<<dim3(BATCH / 32, D / 32, T), tb>>>(out);
}

// round 7
// speedup vs baseline: 1.0292x; 1.0292x over previous
#include <cuda_runtime.h>
#include <math.h>

#define D 128
#define T 64
#define BATCH 512
#define EPS 1e-5f
#define FULLMASK 0xffffffffu

#define SV_STRIDE 129   // row-major v, scalar conflict-free (R3-proven matvec)
#define VT_STRIDE 132   // transposed v, float4-aligned rows, conflict-free

// -------- scratch (device globals; no allocation allowed) --------
__device__ float g_v[D * D];                 // row-normalized W
__device__ float g_rT[(T - 1) * BATCH * D];  // returns transposed: [t][b][d]
__device__ float g_h0T[BATCH * D];           // input[:,0,:] transposed: [b][d]
__device__ float g_outT[T * BATCH * D];      // output transposed: [t][b][d]

// -------- v = W / max(||W_row||, 1e-12) --------
__global__ void prep_v_kernel(const float* __restrict__ W) {
    int i = threadIdx.x;  // row
    float ss = 0.f;
#pragma unroll 8
    for (int j = 0; j < D; j++) {
        float w = W[i * D + j];
        ss += w * w;
    }
    float nrm = fmaxf(sqrtf(ss), 1e-12f);
    for (int j = 0; j < D; j++) g_v[i * D + j] = W[i * D + j] / nrm;
}

// -------- transpose returns (and input t=0 slice) into [t][b][d] --------
__global__ void transpose_in_kernel(const float* __restrict__ inp,
                                    const float* __restrict__ ret) {
    __shared__ float tile[32][33];
    int z = blockIdx.z;
    int b0 = blockIdx.x * 32, d0 = blockIdx.y * 32;
    int tx = threadIdx.x, ty = threadIdx.y;  // (32, 8)
    const float* srcbase;
    float* dst;
    if (z < T - 1) {
        srcbase = ret + (size_t)z * BATCH;
        dst = g_rT + (size_t)z * BATCH * D;
    } else {
        srcbase = inp;
        dst = g_h0T;
    }
#pragma unroll
    for (int i = 0; i < 32; i += 8)
        tile[ty + i][tx] = srcbase[(size_t)(d0 + ty + i) * T * BATCH + (b0 + tx)];
    __syncthreads();
#pragma unroll
    for (int i = 0; i < 32; i += 8)
        dst[(size_t)(b0 + ty + i) * D + (d0 + tx)] = tile[tx][ty + i];
}

// -------- transpose outT [t][b][d] -> out (D,T,B); also emit h_last --------
__global__ void transpose_out_kernel(float* __restrict__ out) {
    __shared__ float tile[32][33];
    int t = blockIdx.z;
    int b0 = blockIdx.x * 32, d0 = blockIdx.y * 32;
    int tx = threadIdx.x, ty = threadIdx.y;
    const float* src = g_outT + (size_t)t * BATCH * D;
#pragma unroll
    for (int i = 0; i < 32; i += 8)
        tile[ty + i][tx] = src[(size_t)(b0 + ty + i) * D + (d0 + tx)];
    __syncthreads();
#pragma unroll
    for (int i = 0; i < 32; i += 8) {
        float val = tile[tx][ty + i];
        int d = d0 + ty + i;
        int b = b0 + tx;
        out[(size_t)d * T * BATCH + (size_t)t * BATCH + b] = val;
        if (t == T - 1)
            out[(size_t)D * T * BATCH + (size_t)d * BATCH + b] = val;
    }
}

// -------- main recurrence: 1 warp per batch column, thread owns 4 dims --------
__global__ void __launch_bounds__(128) rnn_main_kernel(const float* __restrict__ tgt_g,
                                                       const float* __restrict__ b_g) {
    extern __shared__ float smem[];
    float* sv = smem;                       // [128][129] row-major (matvec)
    float* svT = smem + D * SV_STRIDE;      // [128][132] transposed (judge/sweep rows)
    float* wb0 = svT + D * VT_STRIDE;       // per-warp: xw[128], lo[128], hi[128]

    int tid = threadIdx.x, lane = tid & 31, warp = tid >> 5;

    for (int idx = tid; idx < D * D; idx += 128) {
        int r = idx >> 7, c = idx & 127;
        float val = g_v[idx];
        sv[r * SV_STRIDE + c] = val;
        svT[c * VT_STRIDE + r] = val;
    }
    __syncthreads();

    int col = blockIdx.x * 4 + warp;  // grid=128 -> col in [0,512)
    float* xw = wb0 + warp * 384;
    float* lw = xw + 128;
    float* hw = xw + 256;

    float h4[4], tgt4[4], ab4[4], rvd4[4], bp4[4], bn4[4];
#pragma unroll
    for (int q = 0; q < 4; q++) {
        int d = lane + 32 * q;
        tgt4[q] = tgt_g[d];
        ab4[q] = fabsf(b_g[d]);
        rvd4[q] = 1.0f / sv[d * SV_STRIDE + d];
        bp4[q] = ab4[q] + EPS;
        bn4[q] = -ab4[q] - EPS;
        float h0 = g_h0T[(size_t)col * D + d];
        h4[q] = h0;
        g_outT[(size_t)col * D + d] = h0;  // t = 0 slice
    }

    // prefetch r for step t=1 (index 0)
    float rp4[4];
#pragma unroll
    for (int q = 0; q < 4; q++)
        rp4[q] = g_rT[(size_t)col * D + (lane + 32 * q)];

    for (int t = 1; t < T; t++) {
        // ---- adj = h*(1+r) / (1 + sum(h*r)) ----
        float r4[4], adj4[4], x4[4];
        float acc = 0.f;
#pragma unroll
        for (int q = 0; q < 4; q++) {
            r4[q] = rp4[q];
            acc += h4[q] * r4[q];
        }
#pragma unroll
        for (int o = 16; o; o >>= 1) acc += __shfl_xor_sync(FULLMASK, acc, o);
        float inv = 1.0f / (1.0f + acc);
#pragma unroll
        for (int q = 0; q < 4; q++) {
            adj4[q] = h4[q] * (1.0f + r4[q]) * inv;
            x4[q] = adj4[q] - tgt4[q];
            xw[lane + 32 * q] = x4[q];
        }
        __syncwarp();

        // prefetch next step's r while the matvec runs
        if (t < T - 1) {
#pragma unroll
            for (int q = 0; q < 4; q++)
                rp4[q] = g_rT[((size_t)t * BATCH + col) * D + (lane + 32 * q)];
        }

        // ---- s = v @ (adj - pi_bar)  (R3-proven scalar form) ----
        float s4[4] = {0.f, 0.f, 0.f, 0.f};
#pragma unroll 4
        for (int i = 0; i < D; i++) {
            float xi = xw[i];
#pragma unroll
            for (int q = 0; q < 4; q++)
                s4[q] = fmaf(sv[(lane + 32 * q) * SV_STRIDE + i], xi, s4[q]);
        }
        __syncwarp();  // xw reads done before next-iteration writes

        // ---- delta + feas0 ----
        float del4[4];
        bool loc = true;
#pragma unroll
        for (int q = 0; q < 4; q++) {
            float s = s4[q];
            float num = 0.f;
            if (s > ab4[q]) num = ab4[q] - s;
            else if (s < -ab4[q]) num = -ab4[q] - s;
            del4[q] = num * rvd4[q];
            loc = loc && (s < bp4[q]) && (s > bn4[q]);
        }
        bool feas0 = __all_sync(FULLMASK, loc);
        bool judge = feas0;

        unsigned mm[4];
        int ncand = 0;
        if (!judge) {
#pragma unroll
            for (int sl = 0; sl < 4; sl++) {
                mm[sl] = __ballot_sync(FULLMASK, del4[sl] != 0.f);
                ncand += __popc(mm[sl]);
            }
            if (ncand <= 6) {
                // ---- serial judge (few candidates) ----
#pragma unroll
                for (int sl = 0; sl < 4; sl++) {
                    if (judge) continue;
                    unsigned mask = mm[sl];
                    while (mask) {
                        int ln = __ffs(mask) - 1;
                        mask &= mask - 1;
                        float di = __shfl_sync(FULLMASK, del4[sl], ln);
                        int i = sl * 32 + ln;
                        bool ok = true;
#pragma unroll
                        for (int q = 0; q < 4; q++) {
                            float sn = fmaf(svT[i * VT_STRIDE + lane + 32 * q], di, s4[q]);
                            ok = ok && (sn < bp4[q]) && (sn > bn4[q]);
                        }
                        if (__all_sync(FULLMASK, ok)) { judge = true; break; }
                    }
                }
            } else {
                // ---- parallel judge: each lane tests its own candidate ----
                // candidate i feasible <=> v[k][i]*d_i in (bn_k - s_k, bp_k - s_k) forall k
#pragma unroll
                for (int q = 0; q < 4; q++) {
                    lw[lane + 32 * q] = bn4[q] - s4[q];
                    hw[lane + 32 * q] = bp4[q] - s4[q];
                }
                __syncwarp();
                const float4* lo4 = (const float4*)lw;
                const float4* hi4 = (const float4*)hw;
#pragma unroll
                for (int sl = 0; sl < 4; sl++) {
                    if (judge || mm[sl] == 0u) continue;
                    float dd = del4[sl];
                    bool ok = (dd != 0.f);
                    const float4* row4 =
                        (const float4*)(svT + (lane + 32 * sl) * VT_STRIDE);
                    for (int blk = 0; blk < 4; blk++) {
#pragma unroll
                        for (int k4 = blk * 8; k4 < blk * 8 + 8; k4++) {
                            float4 vv = row4[k4];
                            float4 l = lo4[k4];
                            float4 hh = hi4[k4];
                            float p0 = vv.x * dd, p1 = vv.y * dd;
                            float p2 = vv.z * dd, p3 = vv.w * dd;
                            ok = ok && (p0 > l.x) && (p0 < hh.x)
                                    && (p1 > l.y) && (p1 < hh.y)
                                    && (p2 > l.z) && (p2 < hh.z)
                                    && (p3 > l.w) && (p3 < hh.w);
                        }
                        if (!__any_sync(FULLMASK, ok)) break;
                    }
                    if (__any_sync(FULLMASK, ok)) judge = true;
                }
                __syncwarp();  // lw/hw reads done before next-step writes
            }
        }

        float hres4[4];
        if (judge) {
            if (feas0) {
#pragma unroll
                for (int q = 0; q < 4; q++) hres4[q] = adj4[q];
            } else {
                // ---- Gauss-Seidel sweep: ballot-driven, exact vs reference's
                // strictly-increasing single pass.
                float ssl[4], ht4[4];
#pragma unroll
                for (int q = 0; q < 4; q++) { ssl[q] = s4[q]; ht4[q] = adj4[q]; }
#pragma unroll
                for (int sl = 0; sl < 4; sl++) {
                    unsigned eligible = FULLMASK;
                    while (true) {
                        float s = ssl[sl];
                        float num = 0.f;
                        if (s > ab4[sl]) num = ab4[sl] - s;
                        else if (s < -ab4[sl]) num = -ab4[sl] - s;
                        unsigned mask = __ballot_sync(FULLMASK, num != 0.f) & eligible;
                        if (!mask) break;
                        int ln = __ffs(mask) - 1;
                        float cand = num * rvd4[sl];
                        float dj = __shfl_sync(FULLMASK, cand, ln);
                        int j = sl * 32 + ln;
#pragma unroll
                        for (int q = 0; q < 4; q++)
                            ssl[q] = fmaf(svT[j * VT_STRIDE + lane + 32 * q], dj, ssl[q]);
                        if (lane == ln) ht4[sl] += dj;
                        eligible = (ln == 31) ? 0u : (FULLMASK << (ln + 1));
                    }
                }
#pragma unroll
                for (int q = 0; q < 4; q++) hres4[q] = ht4[q];
            }
        } else {
            // ---- bisection collapsed to scalar alpha on segment pi + a*(h-pi)
            float am = __int_as_float(0x7f800000);  // +inf
#pragma unroll
            for (int q = 0; q < 4; q++) {
                float as = fabsf(s4[q]);
                float lim = (as > 0.f) ? bp4[q] / as : __int_as_float(0x7f800000);
                am = fminf(am, lim);
            }
#pragma unroll
            for (int o = 16; o; o >>= 1)
                am = fminf(am, __shfl_xor_sync(FULLMASK, am, o));
            float ain = 0.f, aout = 1.f, amid = 0.5f;
#pragma unroll
            for (int it = 0; it < 10; it++) {
                amid = ain + (aout - ain) * 0.5f;
                if (amid <= am) ain = amid; else aout = amid;
            }
#pragma unroll
            for (int q = 0; q < 4; q++)
                hres4[q] = fmaf(amid, x4[q], tgt4[q]);
        }

#pragma unroll
        for (int q = 0; q < 4; q++) {
            h4[q] = hres4[q];
            g_outT[((size_t)t * BATCH + col) * D + (lane + 32 * q)] = hres4[q];
        }
    }
}

extern "C" void kernel_launch(void* const* d_in, const int* in_sizes, int n_in,
                              void* d_out, int out_size) {
    const float* inp = (const float*)d_in[0];   // (D,T,B)
    const float* tgt = (const float*)d_in[1];   // (D,)
    const float* ret = (const float*)d_in[2];   // (D,T,B)
    // d_in[3] = hidden (unused by reference)
    const float* W = (const float*)d_in[4];     // (D,D)
    const float* bb = (const float*)d_in[5];    // (D,)
    float* out = (float*)d_out;                 // D*T*B output + D*B h_last

    prep_v_kernel<<<1, 128>>>(W);

    dim3 tb(32, 8);
    transpose_in_kernel<<<dim3(BATCH / 32, D / 32, T), tb>>>(inp, ret);

    size_t smem_bytes =
        (size_t)(D * SV_STRIDE + D * VT_STRIDE + 4 * 384) * sizeof(float);
    cudaFuncSetAttribute(rnn_main_kernel,
                         cudaFuncAttributeMaxDynamicSharedMemorySize,
                         (int)smem_bytes);
    rnn_main_kernel<<<128, 128, smem_bytes>>>(tgt, bb);

    transpose_out_kernel<<<dim3(BATCH / 32, D / 32, T), tb>>>(out);
}

// round 9
// speedup vs baseline: 1.7016x; 1.6533x over previous
#include <cuda_runtime.h>
#include <math.h>

#define D 128
#define T 64
#define BATCH 512
#define EPS 1e-5f
#define FULLMASK 0xffffffffu

#define SV_STRIDE 129   // conflict-free rows AND columns (129 mod 32 = 1)

// -------- scratch (device globals; no allocation allowed) --------
__device__ float g_v[D * D];                 // row-normalized W
__device__ float g_rT[(T - 1) * BATCH * D];  // returns transposed: [t][b][d]
__device__ float g_h0T[BATCH * D];           // input[:,0,:] transposed: [b][d]
__device__ float g_outT[T * BATCH * D];      // output transposed: [t][b][d]

// -------- v = W / max(||W_row||, 1e-12) --------
__global__ void prep_v_kernel(const float* __restrict__ W) {
    int i = threadIdx.x;  // row
    float ss = 0.f;
#pragma unroll 8
    for (int j = 0; j < D; j++) {
        float w = W[i * D + j];
        ss += w * w;
    }
    float nrm = fmaxf(sqrtf(ss), 1e-12f);
    for (int j = 0; j < D; j++) g_v[i * D + j] = W[i * D + j] / nrm;
}

// -------- transpose returns (and input t=0 slice) into [t][b][d] --------
__global__ void transpose_in_kernel(const float* __restrict__ inp,
                                    const float* __restrict__ ret) {
    __shared__ float tile[32][33];
    int z = blockIdx.z;
    int b0 = blockIdx.x * 32, d0 = blockIdx.y * 32;
    int tx = threadIdx.x, ty = threadIdx.y;  // (32, 8)
    const float* srcbase;
    float* dst;
    if (z < T - 1) {
        srcbase = ret + (size_t)z * BATCH;
        dst = g_rT + (size_t)z * BATCH * D;
    } else {
        srcbase = inp;
        dst = g_h0T;
    }
#pragma unroll
    for (int i = 0; i < 32; i += 8)
        tile[ty + i][tx] = srcbase[(size_t)(d0 + ty + i) * T * BATCH + (b0 + tx)];
    __syncthreads();
#pragma unroll
    for (int i = 0; i < 32; i += 8)
        dst[(size_t)(b0 + ty + i) * D + (d0 + tx)] = tile[tx][ty + i];
}

// -------- transpose outT [t][b][d] -> out (D,T,B); also emit h_last --------
__global__ void transpose_out_kernel(float* __restrict__ out) {
    __shared__ float tile[32][33];
    int t = blockIdx.z;
    int b0 = blockIdx.x * 32, d0 = blockIdx.y * 32;
    int tx = threadIdx.x, ty = threadIdx.y;
    const float* src = g_outT + (size_t)t * BATCH * D;
#pragma unroll
    for (int i = 0; i < 32; i += 8)
        tile[ty + i][tx] = src[(size_t)(b0 + ty + i) * D + (d0 + tx)];
    __syncthreads();
#pragma unroll
    for (int i = 0; i < 32; i += 8) {
        float val = tile[tx][ty + i];
        int d = d0 + ty + i;
        int b = b0 + tx;
        out[(size_t)d * T * BATCH + (size_t)t * BATCH + b] = val;
        if (t == T - 1)
            out[(size_t)D * T * BATCH + (size_t)d * BATCH + b] = val;
    }
}

// -------- main recurrence: 1 warp per batch column, thread owns 4 dims --------
__global__ void __launch_bounds__(128) rnn_main_kernel(const float* __restrict__ tgt_g,
                                                       const float* __restrict__ b_g) {
    extern __shared__ float smem[];
    float* sv = smem;            // v padded: [128][129]
    float* xb = smem + D * SV_STRIDE;  // per-warp x buffer: [4][128]

    int tid = threadIdx.x, lane = tid & 31, warp = tid >> 5;

    for (int idx = tid; idx < D * D; idx += 128)
        sv[(idx >> 7) * SV_STRIDE + (idx & 127)] = g_v[idx];
    __syncthreads();

    int col = blockIdx.x * 4 + warp;  // grid=128 -> col in [0,512)
    float* xw = xb + warp * D;

    float h4[4], tgt4[4], ab4[4], rvd4[4], bp4[4], bn4[4];
#pragma unroll
    for (int q = 0; q < 4; q++) {
        int d = lane + 32 * q;
        tgt4[q] = tgt_g[d];
        ab4[q] = fabsf(b_g[d]);
        rvd4[q] = 1.0f / sv[d * SV_STRIDE + d];
        bp4[q] = ab4[q] + EPS;
        bn4[q] = -ab4[q] - EPS;
        float h0 = g_h0T[(size_t)col * D + d];
        h4[q] = h0;
        g_outT[(size_t)col * D + d] = h0;  // t = 0 slice
    }

    // prefetch r for step t=1 (index 0)
    float rp4[4];
#pragma unroll
    for (int q = 0; q < 4; q++)
        rp4[q] = g_rT[(size_t)col * D + (lane + 32 * q)];

    for (int t = 1; t < T; t++) {
        // ---- adj = h*(1+r) / (1 + sum(h*r)) ----
        float r4[4], adj4[4], x4[4];
        float acc = 0.f;
#pragma unroll
        for (int q = 0; q < 4; q++) {
            r4[q] = rp4[q];
            acc += h4[q] * r4[q];
        }
#pragma unroll
        for (int o = 16; o; o >>= 1) acc += __shfl_xor_sync(FULLMASK, acc, o);
        float inv = 1.0f / (1.0f + acc);
#pragma unroll
        for (int q = 0; q < 4; q++) {
            adj4[q] = h4[q] * (1.0f + r4[q]) * inv;
            x4[q] = adj4[q] - tgt4[q];
            xw[lane + 32 * q] = x4[q];
        }
        __syncwarp();

        // prefetch next step's r while the matvec runs
        if (t < T - 1) {
#pragma unroll
            for (int q = 0; q < 4; q++)
                rp4[q] = g_rT[((size_t)t * BATCH + col) * D + (lane + 32 * q)];
        }

        // ---- s = v @ (adj - pi_bar)  (R3-proven scalar form) ----
        float s4[4] = {0.f, 0.f, 0.f, 0.f};
#pragma unroll 4
        for (int i = 0; i < D; i++) {
            float xi = xw[i];
#pragma unroll
            for (int q = 0; q < 4; q++)
                s4[q] = fmaf(sv[(lane + 32 * q) * SV_STRIDE + i], xi, s4[q]);
        }
        __syncwarp();  // xw reads done before next-iteration writes

        // ---- delta + feas0 ----
        float del4[4];
        bool loc = true;
#pragma unroll
        for (int q = 0; q < 4; q++) {
            float s = s4[q];
            float num = 0.f;
            if (s > ab4[q]) num = ab4[q] - s;
            else if (s < -ab4[q]) num = -ab4[q] - s;
            del4[q] = num * rvd4[q];
            loc = loc && (s < bp4[q]) && (s > bn4[q]);
        }
        bool feas0 = __all_sync(FULLMASK, loc);
        bool judge = feas0;

        // ---- judge: any single-coordinate fix feasible? ----
        if (!judge) {
            unsigned mm[4];
            int ncand = 0;
#pragma unroll
            for (int sl = 0; sl < 4; sl++) {
                mm[sl] = __ballot_sync(FULLMASK, del4[sl] != 0.f);
                ncand += __popc(mm[sl]);
            }

            if (ncand > 3) {
                // ---- exact screen against one maximally-violated coordinate k*.
                // Rejecting here uses the IDENTICAL fmaf/compare the full test
                // would use for coordinate k*, so judge's boolean is unchanged.
                float mv = 0.f;
#pragma unroll
                for (int q = 0; q < 4; q++)
                    mv = fmaxf(mv, fabsf(s4[q]) - ab4[q]);
                float wv = mv;
#pragma unroll
                for (int o = 16; o; o >>= 1)
                    wv = fmaxf(wv, __shfl_xor_sync(FULLMASK, wv, o));
                int myq = -1;
#pragma unroll
                for (int q = 0; q < 4; q++)
                    if (fabsf(s4[q]) - ab4[q] == wv) myq = q;
                unsigned own = __ballot_sync(FULLMASK, myq >= 0);
                int ln = __ffs(own) - 1;
                int qs = __shfl_sync(FULLMASK, myq, ln);  // uniform slot of k*
                float sA = (qs == 0) ? s4[0] : (qs == 1) ? s4[1] : (qs == 2) ? s4[2] : s4[3];
                float pA = (qs == 0) ? bp4[0] : (qs == 1) ? bp4[1] : (qs == 2) ? bp4[2] : bp4[3];
                float nA = (qs == 0) ? bn4[0] : (qs == 1) ? bn4[1] : (qs == 2) ? bn4[2] : bn4[3];
                float sstar = __shfl_sync(FULLMASK, sA, ln);
                float bpst = __shfl_sync(FULLMASK, pA, ln);
                float bnst = __shfl_sync(FULLMASK, nA, ln);
                int kstar = qs * 32 + ln;
                const float* rowk = sv + (size_t)kstar * SV_STRIDE;
#pragma unroll
                for (int sl = 0; sl < 4; sl++) {
                    float sn = fmaf(rowk[lane + 32 * sl], del4[sl], sstar);
                    bool okc = (del4[sl] != 0.f) && (sn < bpst) && (sn > bnst);
                    mm[sl] = __ballot_sync(FULLMASK, okc);
                }
            }

            // serial full test over (screened) survivors — unchanged semantics
#pragma unroll
            for (int sl = 0; sl < 4; sl++) {
                if (judge) continue;
                unsigned mask = mm[sl];
                while (mask) {
                    int ln = __ffs(mask) - 1;
                    mask &= mask - 1;
                    float di = __shfl_sync(FULLMASK, del4[sl], ln);
                    int i = sl * 32 + ln;
                    bool ok = true;
#pragma unroll
                    for (int q = 0; q < 4; q++) {
                        float sn = fmaf(sv[(lane + 32 * q) * SV_STRIDE + i], di, s4[q]);
                        ok = ok && (sn < bp4[q]) && (sn > bn4[q]);
                    }
                    if (__all_sync(FULLMASK, ok)) { judge = true; break; }
                }
            }
        }

        float hres4[4];
        if (judge) {
            if (feas0) {
#pragma unroll
                for (int q = 0; q < 4; q++) hres4[q] = adj4[q];
            } else {
                // ---- Gauss-Seidel sweep: ballot-driven, exact vs reference's
                // strictly-increasing single pass.
                float ssl[4], ht4[4];
#pragma unroll
                for (int q = 0; q < 4; q++) { ssl[q] = s4[q]; ht4[q] = adj4[q]; }
#pragma unroll
                for (int sl = 0; sl < 4; sl++) {
                    unsigned eligible = FULLMASK;
                    while (true) {
                        float s = ssl[sl];
                        float num = 0.f;
                        if (s > ab4[sl]) num = ab4[sl] - s;
                        else if (s < -ab4[sl]) num = -ab4[sl] - s;
                        unsigned mask = __ballot_sync(FULLMASK, num != 0.f) & eligible;
                        if (!mask) break;
                        int ln = __ffs(mask) - 1;
                        float cand = num * rvd4[sl];
                        float dj = __shfl_sync(FULLMASK, cand, ln);
                        int j = sl * 32 + ln;
#pragma unroll
                        for (int q = 0; q < 4; q++)
                            ssl[q] = fmaf(sv[(lane + 32 * q) * SV_STRIDE + j], dj, ssl[q]);
                        if (lane == ln) ht4[sl] += dj;
                        eligible = (ln == 31) ? 0u : (FULLMASK << (ln + 1));
                    }
                }
#pragma unroll
                for (int q = 0; q < 4; q++) hres4[q] = ht4[q];
            }
        } else {
            // ---- bisection collapsed to scalar alpha on segment pi + a*(h-pi)
            float am = __int_as_float(0x7f800000);  // +inf
#pragma unroll
            for (int q = 0; q < 4; q++) {
                float as = fabsf(s4[q]);
                float lim = (as > 0.f) ? bp4[q] / as : __int_as_float(0x7f800000);
                am = fminf(am, lim);
            }
#pragma unroll
            for (int o = 16; o; o >>= 1)
                am = fminf(am, __shfl_xor_sync(FULLMASK, am, o));
            float ain = 0.f, aout = 1.f, amid = 0.5f;
#pragma unroll
            for (int it = 0; it < 10; it++) {
                amid = ain + (aout - ain) * 0.5f;
                if (amid <= am) ain = amid; else aout = amid;
            }
#pragma unroll
            for (int q = 0; q < 4; q++)
                hres4[q] = fmaf(amid, x4[q], tgt4[q]);
        }

#pragma unroll
        for (int q = 0; q < 4; q++) {
            h4[q] = hres4[q];
            g_outT[((size_t)t * BATCH + col) * D + (lane + 32 * q)] = hres4[q];
        }
    }
}

extern "C" void kernel_launch(void* const* d_in, const int* in_sizes, int n_in,
                              void* d_out, int out_size) {
    const float* inp = (const float*)d_in[0];   // (D,T,B)
    const float* tgt = (const float*)d_in[1];   // (D,)
    const float* ret = (const float*)d_in[2];   // (D,T,B)
    // d_in[3] = hidden (unused by reference)
    const float* W = (const float*)d_in[4];     // (D,D)
    const float* bb = (const float*)d_in[5];    // (D,)
    float* out = (float*)d_out;                 // D*T*B output + D*B h_last

    prep_v_kernel<<<1, 128>>>(W);

    dim3 tb(32, 8);
    transpose_in_kernel<<<dim3(BATCH / 32, D / 32, T), tb>>>(inp, ret);

    size_t smem_bytes = (size_t)(D * SV_STRIDE + 4 * D) * sizeof(float);
    cudaFuncSetAttribute(rnn_main_kernel,
                         cudaFuncAttributeMaxDynamicSharedMemorySize,
                         (int)smem_bytes);
    rnn_main_kernel<<<128, 128, smem_bytes>>>(tgt, bb);

    transpose_out_kernel<<<dim3(BATCH / 32, D / 32, T), tb>>>(out);
}

// round 10
// speedup vs baseline: 1.7770x; 1.0443x over previous
#include <cuda_runtime.h>
#include <math.h>

#define D 128
#define T 64
#define BATCH 512
#define EPS 1e-5f
#define FULLMASK 0xffffffffu

#define SV_STRIDE 129   // conflict-free rows AND columns (129 mod 32 = 1)
#define TB (T * BATCH)

// -------- scratch (device globals; no allocation allowed) --------
__device__ float g_outT[T * BATCH * D];      // output transposed: [t][b][d]

// -------- transpose outT [t][b][d] -> out (D,T,B); also emit h_last --------
__global__ void transpose_out_kernel(float* __restrict__ out) {
    __shared__ float tile[32][33];
    int t = blockIdx.z;
    int b0 = blockIdx.x * 32, d0 = blockIdx.y * 32;
    int tx = threadIdx.x, ty = threadIdx.y;
    const float* src = g_outT + (size_t)t * BATCH * D;
#pragma unroll
    for (int i = 0; i < 32; i += 8)
        tile[ty + i][tx] = src[(size_t)(b0 + ty + i) * D + (d0 + tx)];
    __syncthreads();
#pragma unroll
    for (int i = 0; i < 32; i += 8) {
        float val = tile[tx][ty + i];
        int d = d0 + ty + i;
        int b = b0 + tx;
        out[(size_t)d * TB + (size_t)t * BATCH + b] = val;
        if (t == T - 1)
            out[(size_t)D * TB + (size_t)d * BATCH + b] = val;
    }
}

// -------- main recurrence: 1 warp per batch column, thread owns 4 dims --------
__global__ void __launch_bounds__(128) rnn_main_kernel(const float* __restrict__ inp,
                                                       const float* __restrict__ tgt_g,
                                                       const float* __restrict__ ret,
                                                       const float* __restrict__ W,
                                                       const float* __restrict__ b_g) {
    extern __shared__ float smem[];
    float* sv = smem;                  // v padded: [128][129]
    float* xb = smem + D * SV_STRIDE;  // per-warp x buffer: [4][128]

    int tid = threadIdx.x, lane = tid & 31, warp = tid >> 5;
    int col = blockIdx.x * 4 + warp;  // grid=128 -> col in [0,512)

    // ---- fused prep: thread tid row-normalizes row tid of W into smem.
    // Identical arithmetic to the reference: sum in j-order, sqrt, per-element div.
    {
        const float* wr = W + (size_t)tid * D;
        float ss = 0.f;
#pragma unroll 8
        for (int j = 0; j < D; j++) ss += wr[j] * wr[j];
        float nrm = fmaxf(sqrtf(ss), 1e-12f);
        for (int j = 0; j < D; j++) sv[tid * SV_STRIDE + j] = wr[j] / nrm;
    }

    // h0 / params load overlapped with other threads' v setup (no dependence on sv yet)
    float h4[4], tgt4[4], ab4[4], bp4[4], bn4[4];
#pragma unroll
    for (int q = 0; q < 4; q++) {
        int d = lane + 32 * q;
        tgt4[q] = tgt_g[d];
        ab4[q] = fabsf(b_g[d]);
        bp4[q] = ab4[q] + EPS;
        bn4[q] = -ab4[q] - EPS;
        float h0 = inp[(size_t)d * TB + col];  // input[:,0,:]
        h4[q] = h0;
        g_outT[(size_t)col * D + d] = h0;  // t = 0 slice
    }

    // prefetch r for step t=1 (returns[:,0,:])
    float rp4[4];
#pragma unroll
    for (int q = 0; q < 4; q++)
        rp4[q] = ret[(size_t)(lane + 32 * q) * TB + col];

    __syncthreads();

    float rvd4[4];
#pragma unroll
    for (int q = 0; q < 4; q++) {
        int d = lane + 32 * q;
        rvd4[q] = 1.0f / sv[d * SV_STRIDE + d];
    }

    float* xw = xb + warp * D;

    for (int t = 1; t < T; t++) {
        // ---- adj = h*(1+r) / (1 + sum(h*r)) ----
        float r4[4], adj4[4], x4[4];
        float acc = 0.f;
#pragma unroll
        for (int q = 0; q < 4; q++) {
            r4[q] = rp4[q];
            acc += h4[q] * r4[q];
        }
#pragma unroll
        for (int o = 16; o; o >>= 1) acc += __shfl_xor_sync(FULLMASK, acc, o);
        float inv = 1.0f / (1.0f + acc);
#pragma unroll
        for (int q = 0; q < 4; q++) {
            adj4[q] = h4[q] * (1.0f + r4[q]) * inv;
            x4[q] = adj4[q] - tgt4[q];
            xw[lane + 32 * q] = x4[q];
        }
        __syncwarp();

        // prefetch next step's r (returns[:,t,:]) while the matvec runs
        if (t < T - 1) {
#pragma unroll
            for (int q = 0; q < 4; q++)
                rp4[q] = ret[(size_t)(lane + 32 * q) * TB + (size_t)t * BATCH + col];
        }

        // ---- s = v @ (adj - pi_bar)  (R3-proven scalar form) ----
        float s4[4] = {0.f, 0.f, 0.f, 0.f};
#pragma unroll 4
        for (int i = 0; i < D; i++) {
            float xi = xw[i];
#pragma unroll
            for (int q = 0; q < 4; q++)
                s4[q] = fmaf(sv[(lane + 32 * q) * SV_STRIDE + i], xi, s4[q]);
        }
        __syncwarp();  // xw reads done before next-iteration writes

        // ---- delta + feas0 ----
        float del4[4];
        bool loc = true;
#pragma unroll
        for (int q = 0; q < 4; q++) {
            float s = s4[q];
            float num = 0.f;
            if (s > ab4[q]) num = ab4[q] - s;
            else if (s < -ab4[q]) num = -ab4[q] - s;
            del4[q] = num * rvd4[q];
            loc = loc && (s < bp4[q]) && (s > bn4[q]);
        }
        bool feas0 = __all_sync(FULLMASK, loc);
        bool judge = feas0;

        // ---- judge: any single-coordinate fix feasible? ----
        if (!judge) {
            unsigned mm[4];
            int ncand = 0;
#pragma unroll
            for (int sl = 0; sl < 4; sl++) {
                mm[sl] = __ballot_sync(FULLMASK, del4[sl] != 0.f);
                ncand += __popc(mm[sl]);
            }

            if (ncand > 3) {
                // ---- exact screen against one maximally-violated coordinate k*.
                float mv = 0.f;
#pragma unroll
                for (int q = 0; q < 4; q++)
                    mv = fmaxf(mv, fabsf(s4[q]) - ab4[q]);
                float wv = mv;
#pragma unroll
                for (int o = 16; o; o >>= 1)
                    wv = fmaxf(wv, __shfl_xor_sync(FULLMASK, wv, o));
                int myq = -1;
#pragma unroll
                for (int q = 0; q < 4; q++)
                    if (fabsf(s4[q]) - ab4[q] == wv) myq = q;
                unsigned own = __ballot_sync(FULLMASK, myq >= 0);
                int ln = __ffs(own) - 1;
                int qs = __shfl_sync(FULLMASK, myq, ln);  // uniform slot of k*
                float sA = (qs == 0) ? s4[0] : (qs == 1) ? s4[1] : (qs == 2) ? s4[2] : s4[3];
                float pA = (qs == 0) ? bp4[0] : (qs == 1) ? bp4[1] : (qs == 2) ? bp4[2] : bp4[3];
                float nA = (qs == 0) ? bn4[0] : (qs == 1) ? bn4[1] : (qs == 2) ? bn4[2] : bn4[3];
                float sstar = __shfl_sync(FULLMASK, sA, ln);
                float bpst = __shfl_sync(FULLMASK, pA, ln);
                float bnst = __shfl_sync(FULLMASK, nA, ln);
                int kstar = qs * 32 + ln;
                const float* rowk = sv + (size_t)kstar * SV_STRIDE;
#pragma unroll
                for (int sl = 0; sl < 4; sl++) {
                    float sn = fmaf(rowk[lane + 32 * sl], del4[sl], sstar);
                    bool okc = (del4[sl] != 0.f) && (sn < bpst) && (sn > bnst);
                    mm[sl] = __ballot_sync(FULLMASK, okc);
                }
            }

            // serial full test over (screened) survivors — unchanged semantics
#pragma unroll
            for (int sl = 0; sl < 4; sl++) {
                if (judge) continue;
                unsigned mask = mm[sl];
                while (mask) {
                    int ln = __ffs(mask) - 1;
                    mask &= mask - 1;
                    float di = __shfl_sync(FULLMASK, del4[sl], ln);
                    int i = sl * 32 + ln;
                    bool ok = true;
#pragma unroll
                    for (int q = 0; q < 4; q++) {
                        float sn = fmaf(sv[(lane + 32 * q) * SV_STRIDE + i], di, s4[q]);
                        ok = ok && (sn < bp4[q]) && (sn > bn4[q]);
                    }
                    if (__all_sync(FULLMASK, ok)) { judge = true; break; }
                }
            }
        }

        float hres4[4];
        if (judge) {
            if (feas0) {
#pragma unroll
                for (int q = 0; q < 4; q++) hres4[q] = adj4[q];
            } else {
                // ---- Gauss-Seidel sweep: ballot-driven, exact vs reference's
                // strictly-increasing single pass.
                float ssl[4], ht4[4];
#pragma unroll
                for (int q = 0; q < 4; q++) { ssl[q] = s4[q]; ht4[q] = adj4[q]; }
#pragma unroll
                for (int sl = 0; sl < 4; sl++) {
                    unsigned eligible = FULLMASK;
                    while (true) {
                        float s = ssl[sl];
                        float num = 0.f;
                        if (s > ab4[sl]) num = ab4[sl] - s;
                        else if (s < -ab4[sl]) num = -ab4[sl] - s;
                        unsigned mask = __ballot_sync(FULLMASK, num != 0.f) & eligible;
                        if (!mask) break;
                        int ln = __ffs(mask) - 1;
                        float cand = num * rvd4[sl];
                        float dj = __shfl_sync(FULLMASK, cand, ln);
                        int j = sl * 32 + ln;
#pragma unroll
                        for (int q = 0; q < 4; q++)
                            ssl[q] = fmaf(sv[(lane + 32 * q) * SV_STRIDE + j], dj, ssl[q]);
                        if (lane == ln) ht4[sl] += dj;
                        eligible = (ln == 31) ? 0u : (FULLMASK << (ln + 1));
                    }
                }
#pragma unroll
                for (int q = 0; q < 4; q++) hres4[q] = ht4[q];
            }
        } else {
            // ---- bisection collapsed to scalar alpha on segment pi + a*(h-pi)
            float am = __int_as_float(0x7f800000);  // +inf
#pragma unroll
            for (int q = 0; q < 4; q++) {
                float as = fabsf(s4[q]);
                float lim = (as > 0.f) ? bp4[q] / as : __int_as_float(0x7f800000);
                am = fminf(am, lim);
            }
#pragma unroll
            for (int o = 16; o; o >>= 1)
                am = fminf(am, __shfl_xor_sync(FULLMASK, am, o));
            float ain = 0.f, aout = 1.f, amid = 0.5f;
#pragma unroll
            for (int it = 0; it < 10; it++) {
                amid = ain + (aout - ain) * 0.5f;
                if (amid <= am) ain = amid; else aout = amid;
            }
#pragma unroll
            for (int q = 0; q < 4; q++)
                hres4[q] = fmaf(amid, x4[q], tgt4[q]);
        }

#pragma unroll
        for (int q = 0; q < 4; q++) {
            h4[q] = hres4[q];
            g_outT[((size_t)t * BATCH + col) * D + (lane + 32 * q)] = hres4[q];
        }
    }
}

extern "C" void kernel_launch(void* const* d_in, const int* in_sizes, int n_in,
                              void* d_out, int out_size) {
    const float* inp = (const float*)d_in[0];   // (D,T,B)
    const float* tgt = (const float*)d_in[1];   // (D,)
    const float* ret = (const float*)d_in[2];   // (D,T,B)
    // d_in[3] = hidden (unused by reference)
    const float* W = (const float*)d_in[4];     // (D,D)
    const float* bb = (const float*)d_in[5];    // (D,)
    float* out = (float*)d_out;                 // D*T*B output + D*B h_last

    size_t smem_bytes = (size_t)(D * SV_STRIDE + 4 * D) * sizeof(float);
    cudaFuncSetAttribute(rnn_main_kernel,
                         cudaFuncAttributeMaxDynamicSharedMemorySize,
                         (int)smem_bytes);
    rnn_main_kernel<<<128, 128, smem_bytes>>>(inp, tgt, ret, W, bb);

    dim3 tb(32, 8);
    transpose_out_kernel<<<dim3(BATCH / 32, D / 32, T), tb>>>(out);
}